// round 8
// baseline (speedup 1.0000x reference)
#include <cuda_runtime.h>

#define B_   256
#define T_   250
#define NS   2048
#define H_   256
#define G3   768
#define NSEL 50
#define UBv  0.1f
#define RITER 32

// ---------------- scratch (device globals; no runtime alloc) ----------------
__device__ float g_xg[(size_t)T_ * B_ * G3];     // xg0, later reused as xg1
__device__ float g_hseq[(size_t)T_ * B_ * H_];   // hidden sequence (reused by layer 1)
__device__ float g_att[B_ * NS];
__device__ float g_log[B_ * NS];
__device__ unsigned long long g_slots[128];      // grid-barrier slots

__device__ __forceinline__ float sigmf(float x) { return 1.f / (1.f + expf(-x)); }

// packed fp32x2 helpers — identical numerics to two scalar rn-FMAs
__device__ __forceinline__ unsigned long long dupf(float x) {
    unsigned long long r;
    asm("mov.b64 %0, {%1, %1};" : "=l"(r) : "f"(x));
    return r;
}
#define FFMA2(d, a, b) asm("fma.rn.f32x2 %0, %1, %2, %0;" : "+l"(d) : "l"(a), "l"(b))
#define FADD2(d, a)    asm("add.rn.f32x2 %0, %0, %1;"     : "+l"(d) : "l"(a))
__device__ __forceinline__ void unpack2(unsigned long long v, float& lo, float& hi) {
    asm("mov.b64 {%0, %1}, %2;" : "=f"(lo), "=f"(hi) : "l"(v));
}

// ============================================================================
// fp32 GEMM (FFMA2):  C[M,N] = act( A'[M,K] @ W[N,K]^T + bias[N] )
// permute=1: A row for output row m (= t*256+b) is x row b*250+t.
// BM=128, BN=128, BK=16, 256 threads, 8x8 micro-tile (pairs packed along M).
// ============================================================================
#define BM 128
#define BN 128
#define BK 16
#define ASTR 132
#define WSTR 140
__device__ __forceinline__ int wphys(int c) { return c + ((c >> 5) << 2); }

__device__ __forceinline__ void gemm_tile_compute(
    const float* __restrict__ As, const float* __restrict__ Ws,
    unsigned long long acc2[4][8], int tm, int wcol)
{
#pragma unroll
    for (int k = 0; k < BK; ++k) {
        ulonglong2 a01 = *(const ulonglong2*)&As[k * ASTR + tm * 8];
        ulonglong2 a23 = *(const ulonglong2*)&As[k * ASTR + tm * 8 + 4];
        float4 w0 = *(const float4*)&Ws[k * WSTR + wcol];
        float4 w1 = *(const float4*)&Ws[k * WSTR + wcol + 4];
        unsigned long long wd[8];
        wd[0] = dupf(w0.x); wd[1] = dupf(w0.y); wd[2] = dupf(w0.z); wd[3] = dupf(w0.w);
        wd[4] = dupf(w1.x); wd[5] = dupf(w1.y); wd[6] = dupf(w1.z); wd[7] = dupf(w1.w);
#pragma unroll
        for (int j = 0; j < 8; ++j) {
            FFMA2(acc2[0][j], a01.x, wd[j]);
            FFMA2(acc2[1][j], a01.y, wd[j]);
            FFMA2(acc2[2][j], a23.x, wd[j]);
            FFMA2(acc2[3][j], a23.y, wd[j]);
        }
    }
}

__global__ void __launch_bounds__(256, 2) gemm_kernel(
    const float* __restrict__ A, const float* __restrict__ W,
    const float* __restrict__ bias, float* __restrict__ C,
    int M, int N, int K, int permute, int act)
{
    __shared__ float As[2][BK * ASTR];
    __shared__ float Ws[2][BK * WSTR];
    const int tid = threadIdx.x;
    const int m0 = blockIdx.y * BM;
    const int n0 = blockIdx.x * BN;

    const int lr = tid >> 2;          // 0..63
    const int lk = (tid & 3) << 2;    // 0,4,8,12

    const int mrow0 = m0 + lr;
    const int mrow1 = m0 + lr + 64;
    const long long arow0 = permute ? ((long long)(mrow0 & 255) * T_ + (mrow0 >> 8)) : (long long)mrow0;
    const long long arow1 = permute ? ((long long)(mrow1 & 255) * T_ + (mrow1 >> 8)) : (long long)mrow1;
    const float* pa0 = A + arow0 * K + lk;
    const float* pa1 = A + arow1 * K + lk;
    const float* pw0 = W + (long long)(n0 + lr) * K + lk;
    const float* pw1 = W + (long long)(n0 + lr + 64) * K + lk;

    const int tm = tid >> 4;
    const int tn = tid & 15;
    const int wcol = tn * 8 + ((tn >> 2) << 2);
    const int wc0 = wphys(lr);
    const int wc1 = wphys(lr + 64);

    unsigned long long acc2[4][8];
#pragma unroll
    for (int i = 0; i < 4; ++i)
#pragma unroll
        for (int j = 0; j < 8; ++j) acc2[i][j] = 0ULL;

    {   // chunk 0
        float4 a0 = *(const float4*)pa0;
        float4 a1 = *(const float4*)pa1;
        float4 w0 = *(const float4*)pw0;
        float4 w1 = *(const float4*)pw1;
        float av0[4] = {a0.x, a0.y, a0.z, a0.w};
        float av1[4] = {a1.x, a1.y, a1.z, a1.w};
        float wv0[4] = {w0.x, w0.y, w0.z, w0.w};
        float wv1[4] = {w1.x, w1.y, w1.z, w1.w};
#pragma unroll
        for (int j = 0; j < 4; ++j) {
            As[0][(lk + j) * ASTR + lr]      = av0[j];
            As[0][(lk + j) * ASTR + lr + 64] = av1[j];
            Ws[0][(lk + j) * WSTR + wc0]     = wv0[j];
            Ws[0][(lk + j) * WSTR + wc1]     = wv1[j];
        }
    }
    __syncthreads();

    const int nCh = K / BK;
    for (int c = 1; c < nCh; ++c) {
        const int off = c * BK;
        float4 na0 = *(const float4*)(pa0 + off);
        float4 na1 = *(const float4*)(pa1 + off);
        float4 nw0 = *(const float4*)(pw0 + off);
        float4 nw1 = *(const float4*)(pw1 + off);

        gemm_tile_compute(As[(c - 1) & 1], Ws[(c - 1) & 1], acc2, tm, wcol);

        const int wb = c & 1;
        float av0[4] = {na0.x, na0.y, na0.z, na0.w};
        float av1[4] = {na1.x, na1.y, na1.z, na1.w};
        float wv0[4] = {nw0.x, nw0.y, nw0.z, nw0.w};
        float wv1[4] = {nw1.x, nw1.y, nw1.z, nw1.w};
#pragma unroll
        for (int j = 0; j < 4; ++j) {
            As[wb][(lk + j) * ASTR + lr]      = av0[j];
            As[wb][(lk + j) * ASTR + lr + 64] = av1[j];
            Ws[wb][(lk + j) * WSTR + wc0]     = wv0[j];
            Ws[wb][(lk + j) * WSTR + wc1]     = wv1[j];
        }
        __syncthreads();
    }
    gemm_tile_compute(As[(nCh - 1) & 1], Ws[(nCh - 1) & 1], acc2, tm, wcol);

#pragma unroll
    for (int p = 0; p < 4; ++p) {
        float rowlo[8], rowhi[8];
#pragma unroll
        for (int j = 0; j < 8; ++j) {
            float lo, hi; unpack2(acc2[p][j], lo, hi);
            float bj = bias[n0 + tn * 8 + j];
            lo += bj; hi += bj;
            if (act == 1)      { lo = sigmf(lo); hi = sigmf(hi); }
            else if (act == 2) { lo = lo * sigmf(lo); hi = hi * sigmf(hi); }
            rowlo[j] = lo; rowhi[j] = hi;
        }
        const long long mA = m0 + tm * 8 + 2 * p;
        float* c0 = &C[mA * N + n0 + tn * 8];
        float* c1 = &C[(mA + 1) * N + n0 + tn * 8];
        *(float4*)c0       = make_float4(rowlo[0], rowlo[1], rowlo[2], rowlo[3]);
        *(float4*)(c0 + 4) = make_float4(rowlo[4], rowlo[5], rowlo[6], rowlo[7]);
        *(float4*)c1       = make_float4(rowhi[0], rowhi[1], rowhi[2], rowhi[3]);
        *(float4*)(c1 + 4) = make_float4(rowhi[4], rowhi[5], rowhi[6], rowhi[7]);
    }
}

// ============================================================================
// Persistent GRU scan (contention-free slot barrier)
// Grid 128 blocks = 8 batch-tiles(32) x 16 hcol-tiles(16); 256 threads/block.
// ============================================================================
#define GRU_W2_ULL   (3 * 256 * 16)
#define GRU_HT_F     (256 * 36)
#define GRU_PART_ULL (3 * 64 * 12)
#define GRU_SMEM     (GRU_W2_ULL * 8 + GRU_HT_F * 4 + GRU_PART_ULL * 8)

__global__ void __launch_bounds__(256, 1) gru_scan_kernel(
    const float* __restrict__ Whh, const float* __restrict__ bhh,
    const float* __restrict__ xg, float* __restrict__ hseq)
{
    extern __shared__ char smraw[];
    unsigned long long* w2  = (unsigned long long*)smraw;
    float*              hT  = (float*)(smraw + GRU_W2_ULL * 8);
    unsigned long long* prt = (unsigned long long*)(smraw + GRU_W2_ULL * 8 + GRU_HT_F * 4);

    const int tid = threadIdx.x;
    const int b0 = (blockIdx.x >> 4) * 32;
    const int h0 = (blockIdx.x & 15) * 16;
    const int c  = tid & 15;
    const int g  = (tid >> 4) & 3;
    const int ks = tid >> 6;
    const int r0 = g * 8;
    const int slot = (g << 4) | c;

    for (int idx = tid; idx < 48 * 64; idx += 256) {
        const int row = idx >> 6;
        const int k4  = (idx & 63) << 2;
        const int gate = row >> 4, cc = row & 15;
        float4 wv = *(const float4*)(Whh + (size_t)(gate * H_ + h0 + cc) * H_ + k4);
        w2[(gate * 256 + k4 + 0) * 16 + cc] = dupf(wv.x);
        w2[(gate * 256 + k4 + 1) * 16 + cc] = dupf(wv.y);
        w2[(gate * 256 + k4 + 2) * 16 + cc] = dupf(wv.z);
        w2[(gate * 256 + k4 + 3) * 16 + cc] = dupf(wv.w);
    }
    __syncthreads();

    const int hg = h0 + c;
    const float br = bhh[hg], bz = bhh[H_ + hg], bn = bhh[2 * H_ + hg];
    const int lr  = tid & 31;
    const int lk0 = (tid >> 5) * 32;

    for (int t = 0; t < T_; ++t) {
        unsigned long long aR[4] = {0, 0, 0, 0}, aZ[4] = {0, 0, 0, 0}, aN[4] = {0, 0, 0, 0};
        float xv[3][8];

        if (ks == 0) {
            const float* xrow = xg + (size_t)t * (B_ * G3);
#pragma unroll
            for (int i = 0; i < 8; ++i) {
                const float* xr = xrow + (size_t)(b0 + r0 + i) * G3;
                xv[0][i] = xr[hg];
                xv[1][i] = xr[H_ + hg];
                xv[2][i] = xr[2 * H_ + hg];
            }
        }

        if (t > 0) {
            const float* src = hseq + (size_t)(t - 1) * (B_ * H_)
                                    + (size_t)(b0 + lr) * H_ + lk0;
#pragma unroll
            for (int q = 0; q < 8; ++q) {
                float4 v = __ldcg((const float4*)(src + q * 4));
                const int k = lk0 + q * 4;
                hT[(k + 0) * 36 + lr] = v.x;
                hT[(k + 1) * 36 + lr] = v.y;
                hT[(k + 2) * 36 + lr] = v.z;
                hT[(k + 3) * 36 + lr] = v.w;
            }
            __syncthreads();

            const int kb = ks * 64;
#pragma unroll 4
            for (int kk = 0; kk < 64; ++kk) {
                const int k = kb + kk;
                ulonglong2 a01 = *(const ulonglong2*)&hT[k * 36 + r0];
                ulonglong2 a23 = *(const ulonglong2*)&hT[k * 36 + r0 + 4];
                unsigned long long wr = w2[k * 16 + c];
                unsigned long long wz = w2[(256 + k) * 16 + c];
                unsigned long long wn = w2[(512 + k) * 16 + c];
                FFMA2(aR[0], a01.x, wr); FFMA2(aR[1], a01.y, wr);
                FFMA2(aR[2], a23.x, wr); FFMA2(aR[3], a23.y, wr);
                FFMA2(aZ[0], a01.x, wz); FFMA2(aZ[1], a01.y, wz);
                FFMA2(aZ[2], a23.x, wz); FFMA2(aZ[3], a23.y, wz);
                FFMA2(aN[0], a01.x, wn); FFMA2(aN[1], a01.y, wn);
                FFMA2(aN[2], a23.x, wn); FFMA2(aN[3], a23.y, wn);
            }

            if (ks != 0) {
                unsigned long long* p = prt + ((ks - 1) * 64 + slot) * 12;
#pragma unroll
                for (int i = 0; i < 4; ++i) { p[i] = aR[i]; p[4 + i] = aZ[i]; p[8 + i] = aN[i]; }
            }
            __syncthreads();
            if (ks == 0) {
#pragma unroll
                for (int q = 0; q < 3; ++q) {
                    const unsigned long long* p = prt + (q * 64 + slot) * 12;
#pragma unroll
                    for (int i = 0; i < 4; ++i) {
                        FADD2(aR[i], p[i]); FADD2(aZ[i], p[4 + i]); FADD2(aN[i], p[8 + i]);
                    }
                }
            }
        }

        if (ks == 0) {
            float rr[8], zz[8], nn[8], hold[8];
#pragma unroll
            for (int i = 0; i < 4; ++i) {
                unpack2(aR[i], rr[2 * i], rr[2 * i + 1]);
                unpack2(aZ[i], zz[2 * i], zz[2 * i + 1]);
                unpack2(aN[i], nn[2 * i], nn[2 * i + 1]);
            }
#pragma unroll
            for (int i = 0; i < 8; ++i)
                hold[i] = (t > 0) ? hT[hg * 36 + r0 + i] : 0.f;

            float* hout = hseq + (size_t)t * (B_ * H_);
#pragma unroll
            for (int i = 0; i < 8; ++i) {
                const float r = sigmf(xv[0][i] + rr[i] + br);
                const float z = sigmf(xv[1][i] + zz[i] + bz);
                const float n = tanhf(xv[2][i] + r * (nn[i] + bn));
                hout[(size_t)(b0 + r0 + i) * H_ + hg] = (1.f - z) * n + z * hold[i];
            }
        }

        if (t < T_ - 1) {
            __threadfence();
            __syncthreads();
            if (tid == 0)
                *((volatile unsigned long long*)&g_slots[blockIdx.x]) =
                    (unsigned long long)(t + 1);
            if (tid < 128) {
                volatile unsigned long long* s =
                    (volatile unsigned long long*)&g_slots[tid];
                while (*s <= (unsigned long long)t) { }
            }
            __threadfence();
            __syncthreads();
        }
    }
}

__global__ void reset_sync_kernel() {
    if (threadIdx.x < 128) g_slots[threadIdx.x] = 0ULL;
}

// ============================================================================
// Finalize per batch row: top-50 -> mask; softmax; mask+normalize; rebalance.
// ============================================================================
__global__ void __launch_bounds__(256) finalize_kernel(
    const float* __restrict__ att, const float* __restrict__ logits,
    float* __restrict__ out)
{
    __shared__ float a_s[NS];
    __shared__ float w_s[NS];
    __shared__ unsigned char m_s[NS];
    __shared__ float rf[256];
    __shared__ float rb[256];
    __shared__ int   ri[256];
    __shared__ float sc[8];

    const int b = blockIdx.x;
    const int tid = threadIdx.x;

    for (int n = tid; n < NS; n += 256) {
        a_s[n] = att[(long long)b * NS + n];
        w_s[n] = logits[(long long)b * NS + n];
        m_s[n] = 0;
    }
    if (tid == 0) sc[4] = 0.f;
    __syncthreads();

    for (int it = 0; it < NSEL; ++it) {
        float bv = -3.402823466e38f; int bi = 0x7fffffff;
        for (int n = tid; n < NS; n += 256) {
            float v = a_s[n];
            if (v > bv) { bv = v; bi = n; }
        }
        rf[tid] = bv; ri[tid] = bi;
        __syncthreads();
        for (int s = 128; s > 0; s >>= 1) {
            if (tid < s) {
                float v2 = rf[tid + s]; int i2 = ri[tid + s];
                if (v2 > rf[tid] || (v2 == rf[tid] && i2 < ri[tid])) { rf[tid] = v2; ri[tid] = i2; }
            }
            __syncthreads();
        }
        if (tid == 0) { m_s[ri[0]] = 1; a_s[ri[0]] = -3.402823466e38f; }
        __syncthreads();
    }

    float lm = -3.402823466e38f;
    for (int n = tid; n < NS; n += 256) lm = fmaxf(lm, w_s[n]);
    rf[tid] = lm; __syncthreads();
    for (int s = 128; s > 0; s >>= 1) { if (tid < s) rf[tid] = fmaxf(rf[tid], rf[tid + s]); __syncthreads(); }
    const float Mx = rf[0];
    __syncthreads();

    float ps = 0.f;
    for (int n = tid; n < NS; n += 256) { float e = expf(w_s[n] - Mx); w_s[n] = e; ps += e; }
    rf[tid] = ps; __syncthreads();
    for (int s = 128; s > 0; s >>= 1) { if (tid < s) rf[tid] += rf[tid + s]; __syncthreads(); }
    const float S = rf[0];
    __syncthreads();

    float pm = 0.f;
    for (int n = tid; n < NS; n += 256) {
        float mw = m_s[n] ? (w_s[n] / S) : 0.f;
        w_s[n] = mw; pm += mw;
    }
    rf[tid] = pm; __syncthreads();
    for (int s = 128; s > 0; s >>= 1) { if (tid < s) rf[tid] += rf[tid + s]; __syncthreads(); }
    const float SM = rf[0];
    __syncthreads();

    for (int n = tid; n < NS; n += 256) {
        float w0 = w_s[n] / (SM + 1e-8f);
        a_s[n] = w0;
        w_s[n] = fminf(fmaxf(w0, 0.f), UBv);
    }
    __syncthreads();

    for (int it = 0; it < RITER; ++it) {
        float pl = 0.f, pn = 0.f; int ph = 0;
        for (int n = tid; n < NS; n += 256) {
            float w = w_s[n];
            int nm = (w != UBv) && m_s[n];
            pl += a_s[n] - w;
            if (nm) { pn += w; ph = 1; }
        }
        rf[tid] = pl; rb[tid] = pn; ri[tid] = ph;
        __syncthreads();
        for (int s = 128; s > 0; s >>= 1) {
            if (tid < s) { rf[tid] += rf[tid + s]; rb[tid] += rb[tid + s]; ri[tid] |= ri[tid + s]; }
            __syncthreads();
        }
        if (tid == 0) { sc[0] = rf[0]; sc[1] = rb[0]; sc[2] = ri[0] ? 1.f : 0.f; }
        __syncthreads();

        const float leftover = sc[0];
        const float nsum = sc[1];
        const bool hasnom = (sc[2] != 0.f);
        const bool done = (sc[4] != 0.f);
        const bool upd = (!done) && hasnom;
        const float denom = (nsum == 0.f) ? 1.f : nsum;

        int po = 0;
        for (int n = tid; n < NS; n += 256) {
            float w = w_s[n];
            int nm = (w != UBv) && m_s[n];
            float gift = (leftover * (nm ? w : 0.f)) / denom;
            float w1 = upd ? (w + gift) : w;
            if (w1 > UBv) po = 1;
            w_s[n] = w1;
            if (upd) a_s[n] = w1;
        }
        ri[tid] = po;
        __syncthreads();
        for (int s = 128; s > 0; s >>= 1) { if (tid < s) ri[tid] |= ri[tid + s]; __syncthreads(); }
        const bool over = (ri[0] != 0);
        __syncthreads();

        if (upd && over)
            for (int n = tid; n < NS; n += 256)
                w_s[n] = fminf(fmaxf(w_s[n], 0.f), UBv);
        if (tid == 0) {
            bool d = done || ((!done) && (!hasnom)) || (upd && (!over));
            sc[4] = d ? 1.f : 0.f;
        }
        __syncthreads();
    }

    for (int n = tid; n < NS; n += 256)
        out[(long long)b * NS + n] = w_s[n];
}

// ============================================================================
extern "C" void kernel_launch(void* const* d_in, const int* in_sizes, int n_in,
                              void* d_out, int out_size)
{
    (void)in_sizes; (void)n_in; (void)out_size;
    const float* x    = (const float*)d_in[0];
    const float* Wih0 = (const float*)d_in[1];
    const float* Whh0 = (const float*)d_in[2];
    const float* bih0 = (const float*)d_in[3];
    const float* bhh0 = (const float*)d_in[4];
    const float* Wih1 = (const float*)d_in[5];
    const float* Whh1 = (const float*)d_in[6];
    const float* bih1 = (const float*)d_in[7];
    const float* bhh1 = (const float*)d_in[8];
    const float* Wa   = (const float*)d_in[9];
    const float* ba   = (const float*)d_in[10];
    const float* Wf   = (const float*)d_in[11];
    const float* bf   = (const float*)d_in[12];
    float* out = (float*)d_out;

    float *xg, *hseq, *attb, *logb;
    cudaGetSymbolAddress((void**)&xg,   g_xg);
    cudaGetSymbolAddress((void**)&hseq, g_hseq);
    cudaGetSymbolAddress((void**)&attb, g_att);
    cudaGetSymbolAddress((void**)&logb, g_log);

    cudaFuncSetAttribute(gru_scan_kernel,
                         cudaFuncAttributeMaxDynamicSharedMemorySize, GRU_SMEM);

    const int M = T_ * B_;   // 64000

    // xg0 = permute(x) @ Wih0^T + bih0     [T*B, 768]
    gemm_kernel<<<dim3(G3 / BN, M / BM), 256>>>(x, Wih0, bih0, xg, M, G3, NS, 1, 0);

    // GRU layer 0 (persistent, slot barrier)
    reset_sync_kernel<<<1, 128>>>();
    gru_scan_kernel<<<128, 256, GRU_SMEM>>>(Whh0, bhh0, xg, hseq);

    // xg1 = hseq @ Wih1^T + bih1   (reuse g_xg)
    gemm_kernel<<<dim3(G3 / BN, M / BM), 256>>>(hseq, Wih1, bih1, xg, M, G3, H_, 0, 0);

    // GRU layer 1 (persistent): reuses hseq as its own sequence scratch
    reset_sync_kernel<<<1, 128>>>();
    gru_scan_kernel<<<128, 256, GRU_SMEM>>>(Whh1, bhh1, xg, hseq);

    const float* hT = hseq + (size_t)(T_ - 1) * B_ * H_;

    // att = sigmoid(hT @ Wa^T + ba);  logits = silu(hT @ Wf^T + bf)
    gemm_kernel<<<dim3(NS / BN, B_ / BM), 256>>>(hT, Wa, ba, attb, B_, NS, H_, 0, 1);
    gemm_kernel<<<dim3(NS / BN, B_ / BM), 256>>>(hT, Wf, bf, logb, B_, NS, H_, 0, 2);

    finalize_kernel<<<B_, 256>>>(attb, logb, out);
}

// round 9
// speedup vs baseline: 1.1946x; 1.1946x over previous
#include <cuda_runtime.h>

#define B_   256
#define T_   250
#define NS   2048
#define H_   256
#define G3   768
#define NSEL 50
#define UBv  0.1f
#define RITER 32

// ---------------- scratch (device globals; no runtime alloc) ----------------
__device__ float g_xg[(size_t)T_ * B_ * G3];     // xg0, later reused as xg1
__device__ float g_hseq[(size_t)T_ * B_ * H_];   // hidden sequence (reused by layer 1)
__device__ float g_att[B_ * NS];
__device__ float g_log[B_ * NS];
__device__ unsigned long long g_cnt16[256];      // 16 group counters, 128B apart

__device__ __forceinline__ float sigmf(float x) { return 1.f / (1.f + expf(-x)); }

// packed fp32x2 helpers — identical numerics to two scalar rn-FMAs
__device__ __forceinline__ unsigned long long dupf(float x) {
    unsigned long long r;
    asm("mov.b64 %0, {%1, %1};" : "=l"(r) : "f"(x));
    return r;
}
#define FFMA2(d, a, b) asm("fma.rn.f32x2 %0, %1, %2, %0;" : "+l"(d) : "l"(a), "l"(b))
__device__ __forceinline__ void unpack2(unsigned long long v, float& lo, float& hi) {
    asm("mov.b64 {%0, %1}, %2;" : "=f"(lo), "=f"(hi) : "l"(v));
}

// ============================================================================
// fp32 GEMM (FFMA2):  C[M,N] = act( A'[M,K] @ W[N,K]^T + bias[N] )   [as R6]
// ============================================================================
#define BM 128
#define BN 128
#define BK 16
#define ASTR 132
#define WSTR 140
__device__ __forceinline__ int wphys(int c) { return c + ((c >> 5) << 2); }

__device__ __forceinline__ void gemm_tile_compute(
    const float* __restrict__ As, const float* __restrict__ Ws,
    unsigned long long acc2[4][8], int tm, int wcol)
{
#pragma unroll
    for (int k = 0; k < BK; ++k) {
        ulonglong2 a01 = *(const ulonglong2*)&As[k * ASTR + tm * 8];
        ulonglong2 a23 = *(const ulonglong2*)&As[k * ASTR + tm * 8 + 4];
        float4 w0 = *(const float4*)&Ws[k * WSTR + wcol];
        float4 w1 = *(const float4*)&Ws[k * WSTR + wcol + 4];
        unsigned long long wd[8];
        wd[0] = dupf(w0.x); wd[1] = dupf(w0.y); wd[2] = dupf(w0.z); wd[3] = dupf(w0.w);
        wd[4] = dupf(w1.x); wd[5] = dupf(w1.y); wd[6] = dupf(w1.z); wd[7] = dupf(w1.w);
#pragma unroll
        for (int j = 0; j < 8; ++j) {
            FFMA2(acc2[0][j], a01.x, wd[j]);
            FFMA2(acc2[1][j], a01.y, wd[j]);
            FFMA2(acc2[2][j], a23.x, wd[j]);
            FFMA2(acc2[3][j], a23.y, wd[j]);
        }
    }
}

__global__ void __launch_bounds__(256, 2) gemm_kernel(
    const float* __restrict__ A, const float* __restrict__ W,
    const float* __restrict__ bias, float* __restrict__ C,
    int M, int N, int K, int permute, int act)
{
    __shared__ float As[2][BK * ASTR];
    __shared__ float Ws[2][BK * WSTR];
    const int tid = threadIdx.x;
    const int m0 = blockIdx.y * BM;
    const int n0 = blockIdx.x * BN;

    const int lr = tid >> 2;
    const int lk = (tid & 3) << 2;

    const int mrow0 = m0 + lr;
    const int mrow1 = m0 + lr + 64;
    const long long arow0 = permute ? ((long long)(mrow0 & 255) * T_ + (mrow0 >> 8)) : (long long)mrow0;
    const long long arow1 = permute ? ((long long)(mrow1 & 255) * T_ + (mrow1 >> 8)) : (long long)mrow1;
    const float* pa0 = A + arow0 * K + lk;
    const float* pa1 = A + arow1 * K + lk;
    const float* pw0 = W + (long long)(n0 + lr) * K + lk;
    const float* pw1 = W + (long long)(n0 + lr + 64) * K + lk;

    const int tm = tid >> 4;
    const int tn = tid & 15;
    const int wcol = tn * 8 + ((tn >> 2) << 2);
    const int wc0 = wphys(lr);
    const int wc1 = wphys(lr + 64);

    unsigned long long acc2[4][8];
#pragma unroll
    for (int i = 0; i < 4; ++i)
#pragma unroll
        for (int j = 0; j < 8; ++j) acc2[i][j] = 0ULL;

    {   // chunk 0
        float4 a0 = *(const float4*)pa0;
        float4 a1 = *(const float4*)pa1;
        float4 w0 = *(const float4*)pw0;
        float4 w1 = *(const float4*)pw1;
        float av0[4] = {a0.x, a0.y, a0.z, a0.w};
        float av1[4] = {a1.x, a1.y, a1.z, a1.w};
        float wv0[4] = {w0.x, w0.y, w0.z, w0.w};
        float wv1[4] = {w1.x, w1.y, w1.z, w1.w};
#pragma unroll
        for (int j = 0; j < 4; ++j) {
            As[0][(lk + j) * ASTR + lr]      = av0[j];
            As[0][(lk + j) * ASTR + lr + 64] = av1[j];
            Ws[0][(lk + j) * WSTR + wc0]     = wv0[j];
            Ws[0][(lk + j) * WSTR + wc1]     = wv1[j];
        }
    }
    __syncthreads();

    const int nCh = K / BK;
    for (int c = 1; c < nCh; ++c) {
        const int off = c * BK;
        float4 na0 = *(const float4*)(pa0 + off);
        float4 na1 = *(const float4*)(pa1 + off);
        float4 nw0 = *(const float4*)(pw0 + off);
        float4 nw1 = *(const float4*)(pw1 + off);

        gemm_tile_compute(As[(c - 1) & 1], Ws[(c - 1) & 1], acc2, tm, wcol);

        const int wb = c & 1;
        float av0[4] = {na0.x, na0.y, na0.z, na0.w};
        float av1[4] = {na1.x, na1.y, na1.z, na1.w};
        float wv0[4] = {nw0.x, nw0.y, nw0.z, nw0.w};
        float wv1[4] = {nw1.x, nw1.y, nw1.z, nw1.w};
#pragma unroll
        for (int j = 0; j < 4; ++j) {
            As[wb][(lk + j) * ASTR + lr]      = av0[j];
            As[wb][(lk + j) * ASTR + lr + 64] = av1[j];
            Ws[wb][(lk + j) * WSTR + wc0]     = wv0[j];
            Ws[wb][(lk + j) * WSTR + wc1]     = wv1[j];
        }
        __syncthreads();
    }
    gemm_tile_compute(As[(nCh - 1) & 1], Ws[(nCh - 1) & 1], acc2, tm, wcol);

#pragma unroll
    for (int p = 0; p < 4; ++p) {
        float rowlo[8], rowhi[8];
#pragma unroll
        for (int j = 0; j < 8; ++j) {
            float lo, hi; unpack2(acc2[p][j], lo, hi);
            float bj = bias[n0 + tn * 8 + j];
            lo += bj; hi += bj;
            if (act == 1)      { lo = sigmf(lo); hi = sigmf(hi); }
            else if (act == 2) { lo = lo * sigmf(lo); hi = hi * sigmf(hi); }
            rowlo[j] = lo; rowhi[j] = hi;
        }
        const long long mA = m0 + tm * 8 + 2 * p;
        float* c0 = &C[mA * N + n0 + tn * 8];
        float* c1 = &C[(mA + 1) * N + n0 + tn * 8];
        *(float4*)c0       = make_float4(rowlo[0], rowlo[1], rowlo[2], rowlo[3]);
        *(float4*)(c0 + 4) = make_float4(rowlo[4], rowlo[5], rowlo[6], rowlo[7]);
        *(float4*)c1       = make_float4(rowhi[0], rowhi[1], rowhi[2], rowhi[3]);
        *(float4*)(c1 + 4) = make_float4(rowhi[4], rowhi[5], rowhi[6], rowhi[7]);
    }
}

// ============================================================================
// Persistent GRU scan v3.
// 128 blocks = 16 batch-tiles(16 rows) x 8 hcol-tiles(32 hcols), 256 thr.
// Lane owns (row-pair p = l&7, hcol = 4*warp + (l>>3)); 3 gate accs, full k.
// Weights dup'd f32x2, packed k-pairs: W2[gate][k/2][hcol] = ulonglong2.
// Barrier: one atomic counter per 8-block batch group (independent groups).
// ============================================================================
#define GRU_W2_BYTES (3 * 128 * 32 * 16)     // 196608
#define GRU_HT_BYTES (128 * 8 * 16)          // 16384 (ulonglong2 [k2][p])
#define GRU_SMEM     (GRU_W2_BYTES + GRU_HT_BYTES)

__global__ void __launch_bounds__(256, 1) gru_scan_kernel(
    const float* __restrict__ Whh, const float* __restrict__ bhh,
    const float* __restrict__ xg, float* __restrict__ hseq)
{
    extern __shared__ char smraw[];
    ulonglong2* W2 = (ulonglong2*)smraw;                       // [(g*128+k2)*32 + hcol]
    ulonglong2* A2 = (ulonglong2*)(smraw + GRU_W2_BYTES);      // [k2*8 + p]
    float*      Af = (float*)A2;

    const int tid  = threadIdx.x;
    const int bt   = blockIdx.x >> 3;        // batch group 0..15
    const int ht   = blockIdx.x & 7;         // hcol tile 0..7
    const int b0   = bt * 16;
    const int h0   = ht * 32;
    const int warp = tid >> 5, l = tid & 31;
    const int p    = l & 7;                  // row pair
    const int hcol = warp * 4 + (l >> 3);    // 0..31
    const int hg   = h0 + hcol;

    // ---- one-time weight load: dup + pack k-pairs ----
    for (int idx = tid; idx < 96 * 64; idx += 256) {
        const int row = idx >> 6;            // 0..95: gate*32 + hcol
        const int k4  = (idx & 63) << 2;
        const int gate = row >> 5, hc = row & 31;
        float4 wv = *(const float4*)(Whh + (size_t)(gate * H_ + h0 + hc) * H_ + k4);
        float w[4] = {wv.x, wv.y, wv.z, wv.w};
#pragma unroll
        for (int j = 0; j < 4; j += 2) {
            ulonglong2 u;
            u.x = dupf(w[j]); u.y = dupf(w[j + 1]);
            W2[(gate * 128 + ((k4 + j) >> 1)) * 32 + hc] = u;
        }
    }
    __syncthreads();

    const float br = bhh[hg], bz = bhh[H_ + hg], bn = bhh[2 * H_ + hg];

    // staging map: thread = (r = tid&15, cg = tid>>4), 16 cols each
    const int sr  = tid & 15;
    const int sc0 = (tid >> 4) * 16;

    // prefetch xg for t=0
    float xv[6];
    {
        const float* x0 = xg + (size_t)(b0 + 2 * p) * G3;
        const float* x1 = xg + (size_t)(b0 + 2 * p + 1) * G3;
        xv[0] = x0[hg]; xv[1] = x0[H_ + hg]; xv[2] = x0[2 * H_ + hg];
        xv[3] = x1[hg]; xv[4] = x1[H_ + hg]; xv[5] = x1[2 * H_ + hg];
    }

    unsigned long long* grp = &g_cnt16[bt * 16];

    for (int t = 0; t < T_; ++t) {
        unsigned long long aR = 0ULL, aZ = 0ULL, aN = 0ULL;
        float hold0 = 0.f, hold1 = 0.f;

        if (t > 0) {
            // stage h(t-1)[b0..b0+15][0..255] transposed into A2
            const float* src = hseq + (size_t)(t - 1) * (B_ * H_)
                                    + (size_t)(b0 + sr) * H_ + sc0;
#pragma unroll
            for (int q = 0; q < 4; ++q) {
                float4 v = __ldcg((const float4*)(src + q * 4));
                const int c = sc0 + q * 4;
                float vv[4] = {v.x, v.y, v.z, v.w};
#pragma unroll
                for (int j = 0; j < 4; ++j) {
                    const int cc = c + j;
                    Af[((cc >> 1) * 8 + (sr >> 1)) * 4 + (cc & 1) * 2 + (sr & 1)] = vv[j];
                }
            }
            __syncthreads();

            const ulonglong2* wR = W2 + hcol;
            const ulonglong2* wZ = W2 + 128 * 32 + hcol;
            const ulonglong2* wN = W2 + 256 * 32 + hcol;
            const ulonglong2* Ap = A2 + p;
#pragma unroll 8
            for (int k2 = 0; k2 < 128; ++k2) {
                ulonglong2 av = Ap[k2 * 8];
                ulonglong2 r2 = wR[k2 * 32];
                ulonglong2 z2 = wZ[k2 * 32];
                ulonglong2 n2 = wN[k2 * 32];
                FFMA2(aR, av.x, r2.x); FFMA2(aR, av.y, r2.y);
                FFMA2(aZ, av.x, z2.x); FFMA2(aZ, av.y, z2.y);
                FFMA2(aN, av.x, n2.x); FFMA2(aN, av.y, n2.y);
            }
            // hold = h(t-1)[2p,2p+1][hg]
            hold0 = Af[((hg >> 1) * 8 + p) * 4 + (hg & 1) * 2 + 0];
            hold1 = Af[((hg >> 1) * 8 + p) * 4 + (hg & 1) * 2 + 1];
        }

        // gates for 2 rows
        float r0v, r1v, z0v, z1v, n0v, n1v;
        unpack2(aR, r0v, r1v); unpack2(aZ, z0v, z1v); unpack2(aN, n0v, n1v);

        float* hout = hseq + (size_t)t * (B_ * H_);
        {
            const float r = sigmf(xv[0] + r0v + br);
            const float z = sigmf(xv[1] + z0v + bz);
            const float n = tanhf(xv[2] + r * (n0v + bn));
            hout[(size_t)(b0 + 2 * p) * H_ + hg] = (1.f - z) * n + z * hold0;
        }
        {
            const float r = sigmf(xv[3] + r1v + br);
            const float z = sigmf(xv[4] + z1v + bz);
            const float n = tanhf(xv[5] + r * (n1v + bn));
            hout[(size_t)(b0 + 2 * p + 1) * H_ + hg] = (1.f - z) * n + z * hold1;
        }

        if (t < T_ - 1) {
            // prefetch xg(t+1) before barrier (no cross-block dependency)
            const float* x0 = xg + ((size_t)(t + 1) * B_ + b0 + 2 * p) * G3;
            const float* x1 = x0 + G3;
            xv[0] = x0[hg]; xv[1] = x0[H_ + hg]; xv[2] = x0[2 * H_ + hg];
            xv[3] = x1[hg]; xv[4] = x1[H_ + hg]; xv[5] = x1[2 * H_ + hg];

            __threadfence();
            __syncthreads();
            if (tid == 0) {
                atomicAdd(grp, 1ULL);
                const unsigned long long target =
                    (unsigned long long)(t + 1) * 8ULL;
                volatile unsigned long long* pc =
                    (volatile unsigned long long*)grp;
                while (*pc < target) { }
                __threadfence();
            }
            __syncthreads();
        }
    }
}

__global__ void reset_sync_kernel() {
    if (threadIdx.x < 256) g_cnt16[threadIdx.x] = 0ULL;
}

// ============================================================================
// Finalize per batch row: top-50 -> mask; softmax; mask+normalize; rebalance.
// ============================================================================
__global__ void __launch_bounds__(256) finalize_kernel(
    const float* __restrict__ att, const float* __restrict__ logits,
    float* __restrict__ out)
{
    __shared__ float a_s[NS];
    __shared__ float w_s[NS];
    __shared__ unsigned char m_s[NS];
    __shared__ float rf[256];
    __shared__ float rb[256];
    __shared__ int   ri[256];
    __shared__ float sc[8];

    const int b = blockIdx.x;
    const int tid = threadIdx.x;

    for (int n = tid; n < NS; n += 256) {
        a_s[n] = att[(long long)b * NS + n];
        w_s[n] = logits[(long long)b * NS + n];
        m_s[n] = 0;
    }
    if (tid == 0) sc[4] = 0.f;
    __syncthreads();

    for (int it = 0; it < NSEL; ++it) {
        float bv = -3.402823466e38f; int bi = 0x7fffffff;
        for (int n = tid; n < NS; n += 256) {
            float v = a_s[n];
            if (v > bv) { bv = v; bi = n; }
        }
        rf[tid] = bv; ri[tid] = bi;
        __syncthreads();
        for (int s = 128; s > 0; s >>= 1) {
            if (tid < s) {
                float v2 = rf[tid + s]; int i2 = ri[tid + s];
                if (v2 > rf[tid] || (v2 == rf[tid] && i2 < ri[tid])) { rf[tid] = v2; ri[tid] = i2; }
            }
            __syncthreads();
        }
        if (tid == 0) { m_s[ri[0]] = 1; a_s[ri[0]] = -3.402823466e38f; }
        __syncthreads();
    }

    float lm = -3.402823466e38f;
    for (int n = tid; n < NS; n += 256) lm = fmaxf(lm, w_s[n]);
    rf[tid] = lm; __syncthreads();
    for (int s = 128; s > 0; s >>= 1) { if (tid < s) rf[tid] = fmaxf(rf[tid], rf[tid + s]); __syncthreads(); }
    const float Mx = rf[0];
    __syncthreads();

    float ps = 0.f;
    for (int n = tid; n < NS; n += 256) { float e = expf(w_s[n] - Mx); w_s[n] = e; ps += e; }
    rf[tid] = ps; __syncthreads();
    for (int s = 128; s > 0; s >>= 1) { if (tid < s) rf[tid] += rf[tid + s]; __syncthreads(); }
    const float S = rf[0];
    __syncthreads();

    float pm = 0.f;
    for (int n = tid; n < NS; n += 256) {
        float mw = m_s[n] ? (w_s[n] / S) : 0.f;
        w_s[n] = mw; pm += mw;
    }
    rf[tid] = pm; __syncthreads();
    for (int s = 128; s > 0; s >>= 1) { if (tid < s) rf[tid] += rf[tid + s]; __syncthreads(); }
    const float SM = rf[0];
    __syncthreads();

    for (int n = tid; n < NS; n += 256) {
        float w0 = w_s[n] / (SM + 1e-8f);
        a_s[n] = w0;
        w_s[n] = fminf(fmaxf(w0, 0.f), UBv);
    }
    __syncthreads();

    for (int it = 0; it < RITER; ++it) {
        float pl = 0.f, pn = 0.f; int ph = 0;
        for (int n = tid; n < NS; n += 256) {
            float w = w_s[n];
            int nm = (w != UBv) && m_s[n];
            pl += a_s[n] - w;
            if (nm) { pn += w; ph = 1; }
        }
        rf[tid] = pl; rb[tid] = pn; ri[tid] = ph;
        __syncthreads();
        for (int s = 128; s > 0; s >>= 1) {
            if (tid < s) { rf[tid] += rf[tid + s]; rb[tid] += rb[tid + s]; ri[tid] |= ri[tid + s]; }
            __syncthreads();
        }
        if (tid == 0) { sc[0] = rf[0]; sc[1] = rb[0]; sc[2] = ri[0] ? 1.f : 0.f; }
        __syncthreads();

        const float leftover = sc[0];
        const float nsum = sc[1];
        const bool hasnom = (sc[2] != 0.f);
        const bool done = (sc[4] != 0.f);
        const bool upd = (!done) && hasnom;
        const float denom = (nsum == 0.f) ? 1.f : nsum;

        int po = 0;
        for (int n = tid; n < NS; n += 256) {
            float w = w_s[n];
            int nm = (w != UBv) && m_s[n];
            float gift = (leftover * (nm ? w : 0.f)) / denom;
            float w1 = upd ? (w + gift) : w;
            if (w1 > UBv) po = 1;
            w_s[n] = w1;
            if (upd) a_s[n] = w1;
        }
        ri[tid] = po;
        __syncthreads();
        for (int s = 128; s > 0; s >>= 1) { if (tid < s) ri[tid] |= ri[tid + s]; __syncthreads(); }
        const bool over = (ri[0] != 0);
        __syncthreads();

        if (upd && over)
            for (int n = tid; n < NS; n += 256)
                w_s[n] = fminf(fmaxf(w_s[n], 0.f), UBv);
        if (tid == 0) {
            bool d = done || ((!done) && (!hasnom)) || (upd && (!over));
            sc[4] = d ? 1.f : 0.f;
        }
        __syncthreads();
    }

    for (int n = tid; n < NS; n += 256)
        out[(long long)b * NS + n] = w_s[n];
}

// ============================================================================
extern "C" void kernel_launch(void* const* d_in, const int* in_sizes, int n_in,
                              void* d_out, int out_size)
{
    (void)in_sizes; (void)n_in; (void)out_size;
    const float* x    = (const float*)d_in[0];
    const float* Wih0 = (const float*)d_in[1];
    const float* Whh0 = (const float*)d_in[2];
    const float* bih0 = (const float*)d_in[3];
    const float* bhh0 = (const float*)d_in[4];
    const float* Wih1 = (const float*)d_in[5];
    const float* Whh1 = (const float*)d_in[6];
    const float* bih1 = (const float*)d_in[7];
    const float* bhh1 = (const float*)d_in[8];
    const float* Wa   = (const float*)d_in[9];
    const float* ba   = (const float*)d_in[10];
    const float* Wf   = (const float*)d_in[11];
    const float* bf   = (const float*)d_in[12];
    float* out = (float*)d_out;

    float *xg, *hseq, *attb, *logb;
    cudaGetSymbolAddress((void**)&xg,   g_xg);
    cudaGetSymbolAddress((void**)&hseq, g_hseq);
    cudaGetSymbolAddress((void**)&attb, g_att);
    cudaGetSymbolAddress((void**)&logb, g_log);

    cudaFuncSetAttribute(gru_scan_kernel,
                         cudaFuncAttributeMaxDynamicSharedMemorySize, GRU_SMEM);

    const int M = T_ * B_;   // 64000

    // xg0 = permute(x) @ Wih0^T + bih0     [T*B, 768]
    gemm_kernel<<<dim3(G3 / BN, M / BM), 256>>>(x, Wih0, bih0, xg, M, G3, NS, 1, 0);

    // GRU layer 0 (persistent, per-group barrier)
    reset_sync_kernel<<<1, 256>>>();
    gru_scan_kernel<<<128, 256, GRU_SMEM>>>(Whh0, bhh0, xg, hseq);

    // xg1 = hseq @ Wih1^T + bih1   (reuse g_xg)
    gemm_kernel<<<dim3(G3 / BN, M / BM), 256>>>(hseq, Wih1, bih1, xg, M, G3, H_, 0, 0);

    // GRU layer 1 (persistent): reuses hseq as its own sequence scratch
    reset_sync_kernel<<<1, 256>>>();
    gru_scan_kernel<<<128, 256, GRU_SMEM>>>(Whh1, bhh1, xg, hseq);

    const float* hT = hseq + (size_t)(T_ - 1) * B_ * H_;

    // att = sigmoid(hT @ Wa^T + ba);  logits = silu(hT @ Wf^T + bf)
    gemm_kernel<<<dim3(NS / BN, B_ / BM), 256>>>(hT, Wa, ba, attb, B_, NS, H_, 0, 1);
    gemm_kernel<<<dim3(NS / BN, B_ / BM), 256>>>(hT, Wf, bf, logb, B_, NS, H_, 0, 2);

    finalize_kernel<<<B_, 256>>>(attb, logb, out);
}